// round 4
// baseline (speedup 1.0000x reference)
#include <cuda_runtime.h>

// Problem constants (fixed by reference setup_inputs)
#define BB 128
#define SS 256
#define HH 768
#define KK 64
#define NROWS (BB * SS)       // 32768
#define V4_PER_ROW (HH / 4)   // 192
#define RPB 16                // rows per block
#define NBLK (NROWS / RPB)    // 2048
#define SPLITS (SS / RPB)     // 16 blocks per batch

// One block handles RPB=16 consecutive rows (same batch b).
// Phase 1 (prologue, amortized over 16 rows):
//   - 192 threads load the batch's 3x64 indices into smem (flat [192]).
//   - 12 threads per row scan 16 indices each; hits bit-packed (1=dep,
//     2=dpd, 4=noc) into hits[row] via atomicOr_block (hits are rare).
//   - 16 threads finalize (m0, m1, m2) per row.
// Phase 2: 16 iterations of pure coalesced streaming (1 float4 load,
//   3 float4 stores per thread per row), multipliers via broadcast LDS.
//
// Validity note: indices lie in [0, S) and target = s-1 <= S-2, so
// idx == S-1 never matches -- identical to the reference's (idx+1 < S).
__global__ __launch_bounds__(V4_PER_ROW) void fused_kernel(
    const float4* __restrict__ in,
    const int*    __restrict__ depend,
    const int*    __restrict__ depended,
    const int*    __restrict__ noconn,
    const float*  __restrict__ dep_w,
    const float*  __restrict__ dpd_w,
    float4*       __restrict__ out)
{
    const int bid = blockIdx.x;
    const int b   = bid / SPLITS;           // batch
    const int s0  = (bid % SPLITS) * RPB;   // first row's position
    const int t   = threadIdx.x;

    __shared__ int   sh_idx[3 * KK];        // [0,64)=dep [64,128)=dpd [128,192)=noc
    __shared__ int   sh_hits[RPB];
    __shared__ float sh_m0[RPB], sh_m1[RPB], sh_m2[RPB];

    // load indices (one per thread) + zero hit masks
    if (t < KK)            sh_idx[t] = depend  [b * KK + t];
    else if (t < 2 * KK)   sh_idx[t] = depended[b * KK + (t - KK)];
    else                   sh_idx[t] = noconn  [b * KK + (t - 2 * KK)];
    if (t < RPB) sh_hits[t] = 0;
    __syncthreads();

    // membership: 12 threads per row, 16 indices each
    {
        const int r      = t / 12;           // 0..15
        const int lane   = t - r * 12;       // 0..11
        const int target = s0 + r - 1;       // s=0 -> -1, never matches
        int bits = 0;
#pragma unroll
        for (int k = lane; k < 3 * KK; k += 12) {
            if (sh_idx[k] == target)
                bits |= (k < KK) ? 1 : ((k < 2 * KK) ? 2 : 4);
        }
        if (bits) atomicOr_block(&sh_hits[r], bits);
    }
    __syncthreads();

    // finalize per-row multipliers
    if (t < RPB) {
        const int  hits = sh_hits[t];
        const bool dep  = (hits & 1) != 0;
        const bool dpd  = (hits & 2) != 0;
        const bool noc  = (hits & 4) != 0;
        const bool p0   = (s0 + t == 0);

        sh_m0[t] = (p0 || dep) ? 1.0f : 0.0f;
        sh_m1[t] = (p0 || dpd) ? 1.0f : 0.0f;
        float m2 = dep ? dep_w[b] : 0.0f;
        if (dpd) m2 = dpd_w[b];
        if (noc) m2 = 0.0f;
        if (p0)  m2 = 1.0f;
        sh_m2[t] = m2;
    }
    __syncthreads();

    // stream 16 rows
    const long rowbase = (long)(b * SS + s0) * V4_PER_ROW;
    const long N4      = (long)NROWS * V4_PER_ROW;
#pragma unroll 4
    for (int r = 0; r < RPB; r++) {
        const float m0 = sh_m0[r];
        const float m1 = sh_m1[r];
        const float m2 = sh_m2[r];
        const long  idx = rowbase + (long)r * V4_PER_ROW + t;

        const float4 v = in[idx];
        float4 a, bb, c;
        a.x  = v.x * m0; a.y  = v.y * m0; a.z  = v.z * m0; a.w  = v.w * m0;
        bb.x = v.x * m1; bb.y = v.y * m1; bb.z = v.z * m1; bb.w = v.w * m1;
        c.x  = v.x * m2; c.y  = v.y * m2; c.z  = v.z * m2; c.w  = v.w * m2;

        out[idx]          = a;
        out[N4 + idx]     = bb;
        out[2 * N4 + idx] = c;
    }
}

extern "C" void kernel_launch(void* const* d_in, const int* in_sizes, int n_in,
                              void* d_out, int out_size) {
    const float* bert     = (const float*)d_in[0];
    const int*   depend   = (const int*)d_in[1];
    const int*   depended = (const int*)d_in[2];
    const int*   noconn   = (const int*)d_in[3];
    const float* dep_w    = (const float*)d_in[4];
    const float* dpd_w    = (const float*)d_in[5];
    float*       out      = (float*)d_out;

    fused_kernel<<<NBLK, V4_PER_ROW>>>((const float4*)bert, depend, depended,
                                       noconn, dep_w, dpd_w, (float4*)out);
}

// round 5
// speedup vs baseline: 1.0624x; 1.0624x over previous
#include <cuda_runtime.h>

// Problem constants (fixed by reference setup_inputs)
#define BB 128
#define SS 256
#define HH 768
#define KK 64
#define NROWS (BB * SS)     // 32768
#define V4_PER_ROW (HH / 4) // 192

// One block per (b,s) row, 192 threads (6 warps), one float4 per thread.
//
// Ordering: the streaming input LDG is issued FIRST so its HBM latency
// overlaps the membership work. Membership uses the natural warp layout:
//   warps 0-1 -> depend, warps 2-3 -> depended, warps 4-5 -> no_connect.
// Each warp does one L2-hit index load + one __ballot_sync; lane 0 writes
// a per-warp bool; a single __syncthreads, then all threads combine the 6
// bools via broadcast LDS. No atomics, one barrier.
//
// Validity: indices lie in [0, S) and target = s-1 <= S-2, so idx == S-1
// never matches -- identical to the reference's (idx + 1 < S) check.
__global__ __launch_bounds__(V4_PER_ROW) void fused_kernel(
    const float4* __restrict__ in,
    const int*    __restrict__ depend,
    const int*    __restrict__ depended,
    const int*    __restrict__ noconn,
    const float*  __restrict__ dep_w,
    const float*  __restrict__ dpd_w,
    float4*       __restrict__ out)
{
    const int row = blockIdx.x;
    const int t   = threadIdx.x;

    // 1) issue streaming load immediately (latency overlapped below)
    const long idx = (long)row * V4_PER_ROW + t;
    const float4 v = in[idx];

    // 2) membership (L2-resident index arrays, 96 KB total)
    const int b      = row >> 8;        // row / SS
    const int s      = row & (SS - 1);  // row % SS
    const int target = s - 1;           // s=0 -> -1, never matches (idx >= 0)

    __shared__ int sh_any[6];

    const int k = t & (KK - 1);         // position within the 64-entry list
    const int* lp = (t < KK) ? depend : ((t < 2 * KK) ? depended : noconn);
    const bool match = (__ldg(&lp[b * KK + k]) == target);
    const unsigned bal = __ballot_sync(0xffffffffu, match);
    if ((t & 31) == 0) sh_any[t >> 5] = (bal != 0);
    __syncthreads();

    const bool dep = sh_any[0] | sh_any[1];
    const bool dpd = sh_any[2] | sh_any[3];
    const bool noc = sh_any[4] | sh_any[5];
    const bool p0  = (s == 0);

    const float m0 = (p0 || dep) ? 1.0f : 0.0f;
    const float m1 = (p0 || dpd) ? 1.0f : 0.0f;
    float m2 = dep ? __ldg(&dep_w[b]) : 0.0f;
    if (dpd) m2 = __ldg(&dpd_w[b]);
    if (noc) m2 = 0.0f;
    if (p0)  m2 = 1.0f;

    // 3) multiply + 3 coalesced streaming stores
    float4 a, bb, c;
    a.x  = v.x * m0; a.y  = v.y * m0; a.z  = v.z * m0; a.w  = v.w * m0;
    bb.x = v.x * m1; bb.y = v.y * m1; bb.z = v.z * m1; bb.w = v.w * m1;
    c.x  = v.x * m2; c.y  = v.y * m2; c.z  = v.z * m2; c.w  = v.w * m2;

    const long N4 = (long)NROWS * V4_PER_ROW;
    out[idx]          = a;
    out[N4 + idx]     = bb;
    out[2 * N4 + idx] = c;
}

extern "C" void kernel_launch(void* const* d_in, const int* in_sizes, int n_in,
                              void* d_out, int out_size) {
    const float* bert     = (const float*)d_in[0];
    const int*   depend   = (const int*)d_in[1];
    const int*   depended = (const int*)d_in[2];
    const int*   noconn   = (const int*)d_in[3];
    const float* dep_w    = (const float*)d_in[4];
    const float* dpd_w    = (const float*)d_in[5];
    float*       out      = (float*)d_out;

    fused_kernel<<<NROWS, V4_PER_ROW>>>((const float4*)bert, depend, depended,
                                        noconn, dep_w, dpd_w, (float4*)out);
}